// round 15
// baseline (speedup 1.0000x reference)
#include <cuda_runtime.h>
#include <cstdint>

// NumericalMarkowitz: B=1024, N=128. 1 CTA (128 thr) per item; thread t owns
// row t of Q (64 f32x2 regs). One CTA barrier per FISTA iteration; all warps
// run the projection redundantly. Projection reductions are INTEGER-ONLY on
// the common path: free-coordinate contributions z = v - tau lie in (0,1),
// so they are summed in 2^24 fixed point with one redux.sync.add.u32; masks
// verified locally (active-set stability + vote). No float shfl butterfly.

typedef unsigned long long ull;

#define N_DIM    128
#define N_ITERS  300
#define MW       1.0f
#define EXIT_TOL 1e-6f
#define FPSCALE  16777216.0f          // 2^24
#define FPINV    (1.0f / 16777216.0f)

__device__ __forceinline__ ull pk2(float x, float y) {
    ull r; asm("mov.b64 %0, {%1, %2};" : "=l"(r) : "f"(x), "f"(y)); return r;
}
__device__ __forceinline__ void upk2(ull a, float& x, float& y) {
    asm("mov.b64 {%0, %1}, %2;" : "=f"(x), "=f"(y) : "l"(a));
}
__device__ __forceinline__ ull fma2(ull a, ull b, ull c) {
    ull d; asm("fma.rn.f32x2 %0, %1, %2, %3;" : "=l"(d) : "l"(a), "l"(b), "l"(c)); return d;
}
__device__ __forceinline__ ull mul2(ull a, ull b) {
    ull d; asm("mul.rn.f32x2 %0, %1, %2;" : "=l"(d) : "l"(a), "l"(b)); return d;
}
__device__ __forceinline__ ull add2(ull a, ull b) {
    ull d; asm("add.rn.f32x2 %0, %1, %2;" : "=l"(d) : "l"(a), "l"(b)); return d;
}
__device__ __forceinline__ unsigned wredux_addu(unsigned v) {
    unsigned r; asm volatile("redux.sync.add.u32 %0, %1, 0xffffffff;" : "=r"(r) : "r"(v)); return r;
}
__device__ __forceinline__ float wshfl_add(float v) {
    #pragma unroll
    for (int o = 16; o > 0; o >>= 1) v += __shfl_xor_sync(0xffffffffu, v, o);
    return v;
}

// Dynamic smem (floats): [0,16384) C; [16384,16512) y; [16512,16768) v[2];
// [16768,16772) warp partials for ||Q||_F
#define SMEM_FLOATS (16384 + 128 + 256 + 4)

extern __shared__ float smem_f[];

__global__ void __launch_bounds__(128, 3)
markowitz_kernel(const float* __restrict__ rets,
                 const float* __restrict__ covmat,
                 const float* __restrict__ gamma_sqrt,
                 const float* __restrict__ alpha,
                 float* __restrict__ out)
{
    const int b    = blockIdx.x;
    const int t    = threadIdx.x;
    const int lane = t & 31;
    const int wid  = t >> 5;

    float* sC = smem_f;
    float* sY = smem_f + 16384;
    float* sV = sY + 128;
    float* sR = sV + 256;

    // ---- load C tile ----
    {
        const float4* Cg  = reinterpret_cast<const float4*>(covmat + (size_t)b * (N_DIM * N_DIM));
        float4*       sC4 = reinterpret_cast<float4*>(sC);
        #pragma unroll
        for (int i = 0; i < 32; i++) sC4[i * 128 + t] = Cg[i * 128 + t];
    }
    const float myret = rets[b * N_DIM + t];
    const float g     = gamma_sqrt[b];
    const float g2    = g * g;
    const float aab   = fabsf(alpha[b]);
    __syncthreads();

    // ---- build Q row t ----
    ull q[64];
    #pragma unroll
    for (int j = 0; j < 64; j++) q[j] = 0ULL;

    for (int k = 0; k < N_DIM; k++) {
        const float a  = sC[k * 128 + t];
        const ull   aa = pk2(a, a);
        const ulonglong2* row = reinterpret_cast<const ulonglong2*>(sC + k * 128);
        #pragma unroll
        for (int j = 0; j < 32; j++) {
            ulonglong2 bb = row[j];
            q[2 * j]     = fma2(aa, bb.x, q[2 * j]);
            q[2 * j + 1] = fma2(aa, bb.y, q[2 * j + 1]);
        }
    }
    {
        const ull g2p = pk2(g2, g2);
        #pragma unroll
        for (int j = 0; j < 64; j++) q[j] = mul2(q[j], g2p);
        float x, y; upk2(q[t >> 1], x, y);
        if (t & 1) y += aab; else x += aab;
        q[t >> 1] = pk2(x, y);
    }

    // ---- step = 1 / (2 * ||Q||_F) ----
    {
        ull sacc = 0ULL;
        #pragma unroll
        for (int j = 0; j < 64; j++) sacc = fma2(q[j], q[j], sacc);
        float sx, sy; upk2(sacc, sx, sy);
        float ssq = wshfl_add(sx + sy);
        if (lane == 0) sR[wid] = ssq;
    }
    __syncthreads();
    const float Ssum = sR[0] + sR[1] + sR[2] + sR[3];
    const float step = 1.0f / (2.0f * sqrtf(Ssum));

    // ---- FISTA init ----
    float4 w4 = make_float4(1.0f/128.0f, 1.0f/128.0f, 1.0f/128.0f, 1.0f/128.0f);
    sY[t] = 1.0f / 128.0f;
    float warm = 0.0f;
    float tk   = 1.0f;
    int   p    = 0;
    __syncthreads();

    #pragma unroll 1
    for (int it = 0; it < N_ITERS; it++) {
        // ---- matvec ----
        ull a0 = 0ULL, a1 = 0ULL, a2 = 0ULL, a3 = 0ULL;
        ull a4 = 0ULL, a5 = 0ULL, a6 = 0ULL, a7 = 0ULL;
        const ulonglong2* yy = reinterpret_cast<const ulonglong2*>(sY);
        #pragma unroll
        for (int j = 0; j < 8; j++) {
            ulonglong2 y0 = yy[4 * j];
            ulonglong2 y1 = yy[4 * j + 1];
            ulonglong2 y2 = yy[4 * j + 2];
            ulonglong2 y3 = yy[4 * j + 3];
            a0 = fma2(q[8 * j],     y0.x, a0);
            a1 = fma2(q[8 * j + 1], y0.y, a1);
            a2 = fma2(q[8 * j + 2], y1.x, a2);
            a3 = fma2(q[8 * j + 3], y1.y, a3);
            a4 = fma2(q[8 * j + 4], y2.x, a4);
            a5 = fma2(q[8 * j + 5], y2.y, a5);
            a6 = fma2(q[8 * j + 6], y3.x, a6);
            a7 = fma2(q[8 * j + 7], y3.y, a7);
        }
        a0 = add2(add2(add2(a0, a1), add2(a2, a3)), add2(add2(a4, a5), add2(a6, a7)));
        float ox, oy; upk2(a0, ox, oy);
        const float qy = ox + oy;
        const float yv = sY[t];
        sV[128 * p + t] = fmaf(-step, fmaf(2.0f, qy, -myret), yv);

        const float tn   = 0.5f * (1.0f + sqrtf(fmaf(4.0f * tk, tk, 1.0f)));
        const float coef = (tk - 1.0f) / tn;
        tk = tn;

        __syncthreads();             // the ONLY CTA barrier per iteration

        // ---- projection (all warps, redundant & identical) ----
        const float4 v4 = reinterpret_cast<const float4*>(sV + 128 * p)[lane];

        // local eval: masks (byte), fixed-point sum of z = v - tt over free
        // coords (z in (0,1) by definition), and packed counts (nf | nu<<8).
        auto evalfx = [&](float tt, unsigned& mloc, unsigned& izsum, unsigned& cc) {
            float z; bool f0,f1,f2,f3,u0,u1,u2,u3;
            izsum = 0u; cc = 0u;
            z = v4.x - tt; f0 = (z > 0.0f) && (z < MW); u0 = (z >= MW);
            if (f0) { izsum += (unsigned)__float2int_rn(z * FPSCALE); cc += 1u; } if (u0) cc += (1u << 8);
            z = v4.y - tt; f1 = (z > 0.0f) && (z < MW); u1 = (z >= MW);
            if (f1) { izsum += (unsigned)__float2int_rn(z * FPSCALE); cc += 1u; } if (u1) cc += (1u << 8);
            z = v4.z - tt; f2 = (z > 0.0f) && (z < MW); u2 = (z >= MW);
            if (f2) { izsum += (unsigned)__float2int_rn(z * FPSCALE); cc += 1u; } if (u2) cc += (1u << 8);
            z = v4.w - tt; f3 = (z > 0.0f) && (z < MW); u3 = (z >= MW);
            if (f3) { izsum += (unsigned)__float2int_rn(z * FPSCALE); cc += 1u; } if (u3) cc += (1u << 8);
            mloc = (unsigned)f0 | ((unsigned)f1 << 1) | ((unsigned)f2 << 2) | ((unsigned)f3 << 3)
                 | ((unsigned)u0 << 4) | ((unsigned)u1 << 5) | ((unsigned)u2 << 6) | ((unsigned)u3 << 7);
        };
        auto maskonly = [&](float tt) -> unsigned {
            float z; unsigned m = 0u;
            z = v4.x - tt; m |= (unsigned)((z > 0.0f) && (z < MW)) | ((unsigned)(z >= MW) << 4);
            z = v4.y - tt; m |= ((unsigned)((z > 0.0f) && (z < MW)) << 1) | ((unsigned)(z >= MW) << 5);
            z = v4.z - tt; m |= ((unsigned)((z > 0.0f) && (z < MW)) << 2) | ((unsigned)(z >= MW) << 6);
            z = v4.w - tt; m |= ((unsigned)((z > 0.0f) && (z < MW)) << 3) | ((unsigned)(z >= MW) << 7);
            return m;
        };

        float tau = warm;
        bool  done = false;
        unsigned mfin = 0u;
        float tauf = warm;

        // ---- pass 0: eval at warm tau (2 integer redux), Newton, local verify
        unsigned m_a, iz_a, c_a;
        evalfx(warm, m_a, iz_a, c_a);
        iz_a = wredux_addu(iz_a);
        c_a  = wredux_addu(c_a);
        const int nf0 = (int)(c_a & 255u);
        const int nu0 = (int)((c_a >> 8) & 255u);
        const float fs0 = (float)iz_a * FPINV;        // = sum of (v - warm) over free
        float na = warm;
        if (nf0 > 0) {
            na = warm + (fs0 + (float)nu0 - 1.0f) / (float)nf0;
            const unsigned m_na = maskonly(na);
            if (__all_sync(0xffffffffu, m_na == m_a)) {
                done = true; tau = na; tauf = na; mfin = m_na;
            }
        }

        if (!done) {
            // ---- fallback: bracket + single-point verified search ----
            float mn = fminf(fminf(v4.x, v4.y), fminf(v4.z, v4.w));
            float mx = fmaxf(fmaxf(v4.x, v4.y), fmaxf(v4.z, v4.w));
            #pragma unroll
            for (int o = 16; o > 0; o >>= 1) {
                float s0 = __shfl_xor_sync(0xffffffffu, mn, o);
                float s1 = __shfl_xor_sync(0xffffffffu, mx, o);
                mn = fminf(mn, s0); mx = fmaxf(mx, s1);
            }
            float lo = mn - MW;
            float hi = mx;
            {
                const float s_a = fs0 + (float)nu0;    // s(warm)
                if (s_a > 1.0f) lo = fmaxf(lo, warm); else hi = fminf(hi, warm);
            }
            float tc = (nf0 > 0 && na > lo && na < hi) ? na : 0.5f * (lo + hi);

            #pragma unroll 1
            for (int n = 0; n < 24 && !done; n++) {
                unsigned m_c, iz_c, c_c;
                evalfx(tc, m_c, iz_c, c_c);
                iz_c = wredux_addu(iz_c);
                c_c  = wredux_addu(c_c);
                const int nf2 = (int)(c_c & 255u);
                const int nu2 = (int)((c_c >> 8) & 255u);
                const float fs2 = (float)iz_c * FPINV;
                if (nf2 > 0) {
                    const float na2 = tc + (fs2 + (float)nu2 - 1.0f) / (float)nf2;
                    const unsigned m_na2 = maskonly(na2);
                    if (__all_sync(0xffffffffu, m_na2 == m_c)) {
                        done = true; tau = na2; tauf = na2; mfin = m_na2;
                    } else {
                        const float s_c = fs2 + (float)nu2;
                        if (s_c > 1.0f) lo = fmaxf(lo, tc); else hi = fminf(hi, tc);
                        tc = (na2 > lo && na2 < hi) ? na2 : 0.5f * (lo + hi);
                    }
                } else {
                    const float s_c = (float)nu2;
                    if (s_c > 1.0f) lo = fmaxf(lo, tc); else hi = fminf(hi, tc);
                    tc = 0.5f * (lo + hi);
                }
            }

            if (!done) {
                // exact-form epilogue at tau = tc
                unsigned m_c, iz_c, c_c;
                evalfx(tc, m_c, iz_c, c_c);
                iz_c = wredux_addu(iz_c);
                c_c  = wredux_addu(c_c);
                const int   nf2   = (int)(c_c & 255u);
                const int   nu2   = (int)((c_c >> 8) & 255u);
                const float nfree = (float)(nf2 > 0 ? nf2 : 1);
                tau  = tc;
                tauf = tc + ((float)iz_c * FPINV + (float)nu2 - 1.0f) / nfree;
                mfin = m_c;
            }
        }

        // ---- build w, y from final masks ----
        const bool fr0 = mfin & 1u,  fr1 = mfin & 2u,  fr2 = mfin & 4u,  fr3 = mfin & 8u;
        const bool up0 = mfin & 16u, up1 = mfin & 32u, up2 = mfin & 64u, up3 = mfin & 128u;

        float4 wn, yn;
        wn.x = fr0 ? (v4.x - tauf) : (up0 ? MW : 0.0f);
        wn.y = fr1 ? (v4.y - tauf) : (up1 ? MW : 0.0f);
        wn.z = fr2 ? (v4.z - tauf) : (up2 ? MW : 0.0f);
        wn.w = fr3 ? (v4.w - tauf) : (up3 ? MW : 0.0f);
        yn.x = fmaf(coef, wn.x - w4.x, wn.x);
        yn.y = fmaf(coef, wn.y - w4.y, wn.y);
        yn.z = fmaf(coef, wn.z - w4.z, wn.z);
        yn.w = fmaf(coef, wn.w - w4.w, wn.w);

        reinterpret_cast<float4*>(sY)[lane] = yn;   // redundant identical write
        warm = tau;

        bool okc = (fabsf(wn.x - w4.x) <= EXIT_TOL) && (fabsf(wn.y - w4.y) <= EXIT_TOL)
                && (fabsf(wn.z - w4.z) <= EXIT_TOL) && (fabsf(wn.w - w4.w) <= EXIT_TOL)
                && (fabsf(yn.x - wn.x) <= EXIT_TOL) && (fabsf(yn.y - wn.y) <= EXIT_TOL)
                && (fabsf(yn.z - wn.z) <= EXIT_TOL) && (fabsf(yn.w - wn.w) <= EXIT_TOL);
        const int allok = __all_sync(0xffffffffu, okc);

        w4 = wn;
        p ^= 1;
        __syncwarp();

        if (allok) break;            // identical decision in every warp
    }

    if (wid == 0)
        reinterpret_cast<float4*>(out + (size_t)b * N_DIM)[lane] = w4;
}

extern "C" void kernel_launch(void* const* d_in, const int* in_sizes, int n_in,
                              void* d_out, int out_size)
{
    const float* rets   = (const float*)d_in[0];
    const float* covmat = (const float*)d_in[1];
    const float* gsqrt  = (const float*)d_in[2];
    const float* alph   = (const float*)d_in[3];
    float*       out    = (float*)d_out;

    const int B = in_sizes[2];
    const size_t smem_bytes = SMEM_FLOATS * sizeof(float);

    static bool attr_set = false;
    if (!attr_set) {
        cudaFuncSetAttribute(markowitz_kernel,
                             cudaFuncAttributeMaxDynamicSharedMemorySize,
                             (int)smem_bytes);
        attr_set = true;
    }

    markowitz_kernel<<<B, N_DIM, smem_bytes>>>(rets, covmat, gsqrt, alph, out);
}

// round 16
// speedup vs baseline: 1.4535x; 1.4535x over previous
#include <cuda_runtime.h>
#include <cstdint>

// NumericalMarkowitz: B=1024, N=128. Persistent CTAs (3/SM) pull items from a
// global counter (work stealing smooths heterogeneous FISTA iteration counts).
// Per item: thread t owns row t of Q (64 f32x2 regs); one CTA barrier per
// FISTA iteration; all 4 warps run the projection redundantly; pass 0 Newton
// candidate from the warm-started active set verified locally (mask stability
// + vote); float shfl butterfly for the free-coordinate sum (R15's fixed-point
// variant regressed: quantization noise broke the warm-start verify).

typedef unsigned long long ull;

#define N_DIM    128
#define N_ITERS  300
#define MW       1.0f
#define EXIT_TOL 1e-6f
#define GRID_P   444            // 148 SMs * 3 resident CTAs

__device__ int g_ctr;

__device__ __forceinline__ ull pk2(float x, float y) {
    ull r; asm("mov.b64 %0, {%1, %2};" : "=l"(r) : "f"(x), "f"(y)); return r;
}
__device__ __forceinline__ void upk2(ull a, float& x, float& y) {
    asm("mov.b64 {%0, %1}, %2;" : "=f"(x), "=f"(y) : "l"(a));
}
__device__ __forceinline__ ull fma2(ull a, ull b, ull c) {
    ull d; asm("fma.rn.f32x2 %0, %1, %2, %3;" : "=l"(d) : "l"(a), "l"(b), "l"(c)); return d;
}
__device__ __forceinline__ ull mul2(ull a, ull b) {
    ull d; asm("mul.rn.f32x2 %0, %1, %2;" : "=l"(d) : "l"(a), "l"(b)); return d;
}
__device__ __forceinline__ ull add2(ull a, ull b) {
    ull d; asm("add.rn.f32x2 %0, %1, %2;" : "=l"(d) : "l"(a), "l"(b)); return d;
}
__device__ __forceinline__ unsigned wredux_addu(unsigned v) {
    unsigned r; asm volatile("redux.sync.add.u32 %0, %1, 0xffffffff;" : "=r"(r) : "r"(v)); return r;
}
__device__ __forceinline__ float wshfl_add(float v) {
    #pragma unroll
    for (int o = 16; o > 0; o >>= 1) v += __shfl_xor_sync(0xffffffffu, v, o);
    return v;
}

// Dynamic smem (floats): [0,16384) C; [16384,16512) y; [16512,16768) v[2];
// [16768,16772) warp partials; [16772] item index
#define SMEM_FLOATS (16384 + 128 + 256 + 4 + 1)

extern __shared__ float smem_f[];

__global__ void reset_ctr_kernel() { g_ctr = 0; }

__global__ void __launch_bounds__(128, 3)
markowitz_kernel(const float* __restrict__ rets,
                 const float* __restrict__ covmat,
                 const float* __restrict__ gamma_sqrt,
                 const float* __restrict__ alpha,
                 float* __restrict__ out,
                 int B)
{
    const int t    = threadIdx.x;
    const int lane = t & 31;
    const int wid  = t >> 5;

    float* sC  = smem_f;
    float* sY  = smem_f + 16384;
    float* sV  = sY + 128;
    float* sR  = sV + 256;
    int*   sId = reinterpret_cast<int*>(sR + 4);

    while (true) {
        // ---- grab next item (barrier also separates items' smem use) ----
        if (t == 0) *sId = atomicAdd(&g_ctr, 1);
        __syncthreads();
        const int b = *sId;
        if (b >= B) return;

        // ---- load C tile ----
        {
            const float4* Cg  = reinterpret_cast<const float4*>(covmat + (size_t)b * (N_DIM * N_DIM));
            float4*       sC4 = reinterpret_cast<float4*>(sC);
            #pragma unroll
            for (int i = 0; i < 32; i++) sC4[i * 128 + t] = Cg[i * 128 + t];
        }
        const float myret = rets[b * N_DIM + t];
        const float g     = gamma_sqrt[b];
        const float g2    = g * g;
        const float aab   = fabsf(alpha[b]);
        __syncthreads();

        // ---- build Q row t ----
        ull q[64];
        #pragma unroll
        for (int j = 0; j < 64; j++) q[j] = 0ULL;

        for (int k = 0; k < N_DIM; k++) {
            const float a  = sC[k * 128 + t];
            const ull   aa = pk2(a, a);
            const ulonglong2* row = reinterpret_cast<const ulonglong2*>(sC + k * 128);
            #pragma unroll
            for (int j = 0; j < 32; j++) {
                ulonglong2 bb = row[j];
                q[2 * j]     = fma2(aa, bb.x, q[2 * j]);
                q[2 * j + 1] = fma2(aa, bb.y, q[2 * j + 1]);
            }
        }
        {
            const ull g2p = pk2(g2, g2);
            #pragma unroll
            for (int j = 0; j < 64; j++) q[j] = mul2(q[j], g2p);
            float x, y; upk2(q[t >> 1], x, y);
            if (t & 1) y += aab; else x += aab;
            q[t >> 1] = pk2(x, y);
        }

        // ---- step = 1 / (2 * ||Q||_F) ----
        {
            ull sacc = 0ULL;
            #pragma unroll
            for (int j = 0; j < 64; j++) sacc = fma2(q[j], q[j], sacc);
            float sx, sy; upk2(sacc, sx, sy);
            float ssq = wshfl_add(sx + sy);
            if (lane == 0) sR[wid] = ssq;
        }
        __syncthreads();
        const float Ssum = sR[0] + sR[1] + sR[2] + sR[3];
        const float step = 1.0f / (2.0f * sqrtf(Ssum));

        // ---- FISTA init ----
        float4 w4 = make_float4(1.0f/128.0f, 1.0f/128.0f, 1.0f/128.0f, 1.0f/128.0f);
        sY[t] = 1.0f / 128.0f;
        float warm = 0.0f;
        float tk   = 1.0f;
        int   p    = 0;
        __syncthreads();

        #pragma unroll 1
        for (int it = 0; it < N_ITERS; it++) {
            // ---- matvec ----
            ull a0 = 0ULL, a1 = 0ULL, a2 = 0ULL, a3 = 0ULL;
            ull a4 = 0ULL, a5 = 0ULL, a6 = 0ULL, a7 = 0ULL;
            const ulonglong2* yy = reinterpret_cast<const ulonglong2*>(sY);
            #pragma unroll
            for (int j = 0; j < 8; j++) {
                ulonglong2 y0 = yy[4 * j];
                ulonglong2 y1 = yy[4 * j + 1];
                ulonglong2 y2 = yy[4 * j + 2];
                ulonglong2 y3 = yy[4 * j + 3];
                a0 = fma2(q[8 * j],     y0.x, a0);
                a1 = fma2(q[8 * j + 1], y0.y, a1);
                a2 = fma2(q[8 * j + 2], y1.x, a2);
                a3 = fma2(q[8 * j + 3], y1.y, a3);
                a4 = fma2(q[8 * j + 4], y2.x, a4);
                a5 = fma2(q[8 * j + 5], y2.y, a5);
                a6 = fma2(q[8 * j + 6], y3.x, a6);
                a7 = fma2(q[8 * j + 7], y3.y, a7);
            }
            a0 = add2(add2(add2(a0, a1), add2(a2, a3)), add2(add2(a4, a5), add2(a6, a7)));
            float ox, oy; upk2(a0, ox, oy);
            const float qy = ox + oy;
            const float yv = sY[t];
            sV[128 * p + t] = fmaf(-step, fmaf(2.0f, qy, -myret), yv);

            const float tn   = 0.5f * (1.0f + sqrtf(fmaf(4.0f * tk, tk, 1.0f)));
            const float coef = (tk - 1.0f) / tn;
            tk = tn;

            __syncthreads();             // the ONLY CTA barrier per iteration

            // ---- projection (all warps, redundant & identical) ----
            const float4 v4 = reinterpret_cast<const float4*>(sV + 128 * p)[lane];

            auto evalm = [&](float tt, unsigned& mloc, float& ls, unsigned& cc) {
                float z; bool f0,f1,f2,f3,u0,u1,u2,u3;
                z = v4.x - tt; f0 = (z > 0.0f) && (z < MW); u0 = (z >= MW);
                z = v4.y - tt; f1 = (z > 0.0f) && (z < MW); u1 = (z >= MW);
                z = v4.z - tt; f2 = (z > 0.0f) && (z < MW); u2 = (z >= MW);
                z = v4.w - tt; f3 = (z > 0.0f) && (z < MW); u3 = (z >= MW);
                ls = 0.0f; cc = 0u;
                if (f0) { ls += v4.x; cc += 1u; } if (u0) cc += (1u << 8);
                if (f1) { ls += v4.y; cc += 1u; } if (u1) cc += (1u << 8);
                if (f2) { ls += v4.z; cc += 1u; } if (u2) cc += (1u << 8);
                if (f3) { ls += v4.w; cc += 1u; } if (u3) cc += (1u << 8);
                mloc = (unsigned)f0 | ((unsigned)f1 << 1) | ((unsigned)f2 << 2) | ((unsigned)f3 << 3)
                     | ((unsigned)u0 << 4) | ((unsigned)u1 << 5) | ((unsigned)u2 << 6) | ((unsigned)u3 << 7);
            };
            auto maskonly = [&](float tt) -> unsigned {
                float z; unsigned m = 0u;
                z = v4.x - tt; m |= (unsigned)((z > 0.0f) && (z < MW)) | ((unsigned)(z >= MW) << 4);
                z = v4.y - tt; m |= ((unsigned)((z > 0.0f) && (z < MW)) << 1) | ((unsigned)(z >= MW) << 5);
                z = v4.z - tt; m |= ((unsigned)((z > 0.0f) && (z < MW)) << 2) | ((unsigned)(z >= MW) << 6);
                z = v4.w - tt; m |= ((unsigned)((z > 0.0f) && (z < MW)) << 3) | ((unsigned)(z >= MW) << 7);
                return m;
            };

            float tau = warm;
            bool  done = false;
            unsigned mfin = 0u;
            float tauf = warm;

            // ---- pass 0: eval at warm tau, Newton candidate, local verify ----
            unsigned m_a, c_a; float ls_a;
            evalm(warm, m_a, ls_a, c_a);
            c_a = wredux_addu(c_a);
            float sv = wshfl_add(ls_a);
            const int nf0 = (int)(c_a & 255u);
            const int nu0 = (int)((c_a >> 8) & 255u);
            float na = warm;
            if (nf0 > 0) {
                na = (sv + (float)nu0 - 1.0f) / (float)nf0;
                const unsigned m_na = maskonly(na);
                if (__all_sync(0xffffffffu, m_na == m_a)) {
                    done = true; tau = na; tauf = na; mfin = m_na;
                }
            }

            if (!done) {
                // ---- fallback: bracket + single-point verified search ----
                float mn = fminf(fminf(v4.x, v4.y), fminf(v4.z, v4.w));
                float mx = fmaxf(fmaxf(v4.x, v4.y), fmaxf(v4.z, v4.w));
                #pragma unroll
                for (int o = 16; o > 0; o >>= 1) {
                    float s0 = __shfl_xor_sync(0xffffffffu, mn, o);
                    float s1 = __shfl_xor_sync(0xffffffffu, mx, o);
                    mn = fminf(mn, s0); mx = fmaxf(mx, s1);
                }
                float lo = mn - MW;
                float hi = mx;
                {
                    const float s_a = sv - (float)nf0 * warm + (float)nu0;
                    if (s_a > 1.0f) lo = fmaxf(lo, warm); else hi = fminf(hi, warm);
                }
                float tc = (nf0 > 0 && na > lo && na < hi) ? na : 0.5f * (lo + hi);

                unsigned m_c = 0u; unsigned c_c; float ls_c;
                #pragma unroll 1
                for (int n = 0; n < 24 && !done; n++) {
                    evalm(tc, m_c, ls_c, c_c);
                    c_c = wredux_addu(c_c);
                    float s2 = wshfl_add(ls_c);
                    const int nf2 = (int)(c_c & 255u);
                    const int nu2 = (int)((c_c >> 8) & 255u);
                    if (nf2 > 0) {
                        const float na2 = (s2 + (float)nu2 - 1.0f) / (float)nf2;
                        const unsigned m_na2 = maskonly(na2);
                        if (__all_sync(0xffffffffu, m_na2 == m_c)) {
                            done = true; tau = na2; tauf = na2; mfin = m_na2;
                        } else {
                            const float s_c = s2 - (float)nf2 * tc + (float)nu2;
                            if (s_c > 1.0f) lo = fmaxf(lo, tc); else hi = fminf(hi, tc);
                            tc = (na2 > lo && na2 < hi) ? na2 : 0.5f * (lo + hi);
                        }
                    } else {
                        const float s_c = (float)nu2;
                        if (s_c > 1.0f) lo = fmaxf(lo, tc); else hi = fminf(hi, tc);
                        tc = 0.5f * (lo + hi);
                    }
                }

                if (!done) {
                    evalm(tc, m_c, ls_c, c_c);
                    c_c = wredux_addu(c_c);
                    float s2 = wshfl_add(ls_c);
                    const int   nf2   = (int)(c_c & 255u);
                    const int   nu2   = (int)((c_c >> 8) & 255u);
                    const float nfree = (float)(nf2 > 0 ? nf2 : 1);
                    tau  = tc;
                    tauf = (s2 + (float)nu2 - 1.0f) / nfree;
                    mfin = m_c;
                }
            }

            // ---- build w, y from final masks ----
            const bool fr0 = mfin & 1u,  fr1 = mfin & 2u,  fr2 = mfin & 4u,  fr3 = mfin & 8u;
            const bool up0 = mfin & 16u, up1 = mfin & 32u, up2 = mfin & 64u, up3 = mfin & 128u;

            float4 wn, yn;
            wn.x = fr0 ? (v4.x - tauf) : (up0 ? MW : 0.0f);
            wn.y = fr1 ? (v4.y - tauf) : (up1 ? MW : 0.0f);
            wn.z = fr2 ? (v4.z - tauf) : (up2 ? MW : 0.0f);
            wn.w = fr3 ? (v4.w - tauf) : (up3 ? MW : 0.0f);
            yn.x = fmaf(coef, wn.x - w4.x, wn.x);
            yn.y = fmaf(coef, wn.y - w4.y, wn.y);
            yn.z = fmaf(coef, wn.z - w4.z, wn.z);
            yn.w = fmaf(coef, wn.w - w4.w, wn.w);

            reinterpret_cast<float4*>(sY)[lane] = yn;   // redundant identical write
            warm = tau;

            bool okc = (fabsf(wn.x - w4.x) <= EXIT_TOL) && (fabsf(wn.y - w4.y) <= EXIT_TOL)
                    && (fabsf(wn.z - w4.z) <= EXIT_TOL) && (fabsf(wn.w - w4.w) <= EXIT_TOL)
                    && (fabsf(yn.x - wn.x) <= EXIT_TOL) && (fabsf(yn.y - wn.y) <= EXIT_TOL)
                    && (fabsf(yn.z - wn.z) <= EXIT_TOL) && (fabsf(yn.w - wn.w) <= EXIT_TOL);
            const int allok = __all_sync(0xffffffffu, okc);

            w4 = wn;
            p ^= 1;
            __syncwarp();

            if (allok) break;            // identical decision in every warp
        }

        if (wid == 0)
            reinterpret_cast<float4*>(out + (size_t)b * N_DIM)[lane] = w4;
        // item-boundary barrier happens at top of loop (idx broadcast)
    }
}

extern "C" void kernel_launch(void* const* d_in, const int* in_sizes, int n_in,
                              void* d_out, int out_size)
{
    const float* rets   = (const float*)d_in[0];
    const float* covmat = (const float*)d_in[1];
    const float* gsqrt  = (const float*)d_in[2];
    const float* alph   = (const float*)d_in[3];
    float*       out    = (float*)d_out;

    const int B = in_sizes[2];
    const size_t smem_bytes = SMEM_FLOATS * sizeof(float);

    static bool attr_set = false;
    if (!attr_set) {
        cudaFuncSetAttribute(markowitz_kernel,
                             cudaFuncAttributeMaxDynamicSharedMemorySize,
                             (int)smem_bytes);
        attr_set = true;
    }

    reset_ctr_kernel<<<1, 1>>>();
    const int grid = (B < GRID_P) ? B : GRID_P;
    markowitz_kernel<<<grid, N_DIM, smem_bytes>>>(rets, covmat, gsqrt, alph, out, B);
}